// round 17
// baseline (speedup 1.0000x reference)
#include <cuda_runtime.h>
#include <cuda_bf16.h>
#include <math.h>

#define BTT 192            // B*T
#define NNODE 207
#define DMODEL 256
#define NHEADS 8
#define DHEAD 32
#define MTOT (BTT * NNODE) // 39744

// weight offsets in k-PAIR units inside g_W2 (uint2 = packed bf16 hi,lo pair)
#define OFFP_WQ 0
#define OFFP_WK 32768
#define OFFP_WV 65536
#define OFFP_WP 98304
#define OFFP_WG 131072
#define WP_TOTAL 196608

// ---------------- scratch -------------------------------------------------
__device__ float g_Q [MTOT * DMODEL];
__device__ float g_K [MTOT * DMODEL];
__device__ float g_V [MTOT * DMODEL];
__device__ float g_Zi[MTOT * DMODEL];
__device__ float g_Zj[MTOT * DMODEL];
__device__ float g_Zc[MTOT * DMODEL];
__device__ uint2 g_W2[WP_TOTAL];   // [kp][n]: .x = {bf16 hi k, hi k+1}, .y = lo pair

// ---------------- bf16 helpers ----------------------------------------------
__device__ __forceinline__ unsigned bf16pack(float a, float b) {
    __nv_bfloat162 t = __floats2bfloat162_rn(a, b);   // a -> low 16 bits
    return *(unsigned*)&t;
}
__device__ __forceinline__ void bsplit2(float a, float b, unsigned& hi, unsigned& lo) {
    float ha = __bfloat162float(__float2bfloat16_rn(a));
    float hb = __bfloat162float(__float2bfloat16_rn(b));
    hi = bf16pack(ha, hb);
    lo = bf16pack(a - ha, b - hb);
}
__device__ __forceinline__ void mma_bf16(float4& c, const unsigned a[4], const unsigned b[2]) {
    asm volatile(
        "mma.sync.aligned.m16n8k16.row.col.f32.bf16.bf16.f32 "
        "{%0,%1,%2,%3}, {%4,%5,%6,%7}, {%8,%9}, {%0,%1,%2,%3};"
        : "+f"(c.x), "+f"(c.y), "+f"(c.z), "+f"(c.w)
        : "r"(a[0]), "r"(a[1]), "r"(a[2]), "r"(a[3]), "r"(b[0]), "r"(b[1]));
}
__device__ __forceinline__ void cp16(void* s, const void* g) {
    unsigned sa = (unsigned)__cvta_generic_to_shared(s);
    asm volatile("cp.async.cg.shared.global [%0], [%1], 16;\n" :: "r"(sa), "l"(g));
}
template<int N_> __device__ __forceinline__ void cp_wait() {
    asm volatile("cp.async.wait_group %0;\n" :: "n"(N_));
}
__device__ __forceinline__ void cp_commit() {
    asm volatile("cp.async.commit_group;\n");
}

// ---------------- weight pre-split (bf16 hi/lo packed k-pairs) ---------------
__global__ __launch_bounds__(256)
void split_weights(const float* __restrict__ Wq, const float* __restrict__ Wk,
                   const float* __restrict__ Wv, const float* __restrict__ Wp,
                   const float* __restrict__ Wg)
{
    int i = blockIdx.x * 256 + threadIdx.x;
    if (i >= WP_TOTAL) return;
    const float* src; int off;
    if      (i < OFFP_WK) { src = Wq; off = OFFP_WQ; }
    else if (i < OFFP_WV) { src = Wk; off = OFFP_WK; }
    else if (i < OFFP_WP) { src = Wv; off = OFFP_WV; }
    else if (i < OFFP_WG) { src = Wp; off = OFFP_WP; }
    else                  { src = Wg; off = OFFP_WG; }
    int local = i - off;
    int kp = local >> 8;          // k-pair row
    int n  = local & 255;
    float w0 = src[(size_t)(2 * kp) * DMODEL + n];
    float w1 = src[(size_t)(2 * kp + 1) * DMODEL + n];
    unsigned hi, lo;
    bsplit2(w0, w1, hi, lo);
    g_W2[i] = make_uint2(hi, lo);
}

// ---------------- tensor-core GEMM (3xBF16, m16n8k16), 2 CTAs/SM -------------
// (round-16 winner, unchanged)
#define GBM 128
#define GBN 128
#define GBK 32
#define AS2_LD 20                              // uint2 stride, A [128][20]
#define BS2_LD 132                             // uint2 stride, B [16][132]
#define STG_A_BYTES (GBM * AS2_LD * 8)         // 20480
#define STG_B_BYTES (16 * BS2_LD * 8)          // 16896
#define STAGE_BYTES (STG_A_BYTES + STG_B_BYTES)// 37376
#define GEMM_SMEM (2 * STAGE_BYTES)            // 74752

template<int MODE>
__global__ __launch_bounds__(256, 2)
void gemm_tc(const float* __restrict__ A0, const float* __restrict__ A1,
             const uint2* __restrict__ BwBase,
             const float* __restrict__ b0, const float* __restrict__ b1,
             const float* __restrict__ b2,
             const float* __restrict__ Zi, const float* __restrict__ Zj,
             float* __restrict__ C0, float* __restrict__ C1, float* __restrict__ C2,
             int M, int K)
{
    extern __shared__ char sm[];

    const int N = DMODEL;

    const int sel = (MODE == 2) ? (blockIdx.y >> 1) : 0;
    const int bn  = (MODE == 2) ? (blockIdx.y & 1) * GBN : blockIdx.y * GBN;
    const uint2* Bw = BwBase + (MODE == 2 ? sel * 32768 : 0);
    const float* bias = (MODE == 2) ? (sel == 0 ? b0 : (sel == 1 ? b1 : b2)) : b0;
    float* C          = (MODE == 2) ? (sel == 0 ? C0 : (sel == 1 ? C1 : C2)) : C0;

    const int bm = blockIdx.x * GBM;
    const int tid  = threadIdx.x;
    const int wid  = tid >> 5;
    const int lane = tid & 31;
    const int rb = (wid >> 2) * 64;
    const int cb = (wid & 3) * 32;
    const int g   = lane >> 2;
    const int tig = lane & 3;

    float4 apf[4];

    float4 acc[4][4];
#pragma unroll
    for (int mt = 0; mt < 4; mt++)
#pragma unroll
        for (int nt = 0; nt < 4; nt++) acc[mt][nt] = make_float4(0.f, 0.f, 0.f, 0.f);

    auto stageA = [&](int s) { return (uint2*)(sm + s * STAGE_BYTES); };
    auto stageB = [&](int s) { return (uint2*)(sm + s * STAGE_BYTES + STG_A_BYTES); };

    auto ldgA = [&](int kt) {
#pragma unroll
        for (int i = 0; i < 4; i++) {
            int idx = tid + i * 256;
            int row = idx >> 3;
            int c4  = idx & 7;
            int gm  = bm + row;
            int gk  = kt + c4 * 4;
            float4 v = make_float4(0.f, 0.f, 0.f, 0.f);
            if (gm < M) {
                if (MODE == 1) {
                    const float* Ap = (gk < DMODEL) ? A0 : A1;
                    int col = gk & (DMODEL - 1);
                    v = *(const float4*)&Ap[(size_t)gm * DMODEL + col];
                } else {
                    v = *(const float4*)&A0[(size_t)gm * K + gk];
                }
            }
            apf[i] = v;
        }
    };
    auto issueB = [&](int kt, int s) {
        uint2* Bs2 = stageB(s);
        const int ktp = kt >> 1;
#pragma unroll
        for (int i = 0; i < 4; i++) {
            int idx = tid + i * 256;
            int row = idx >> 6;
            int ch  = idx & 63;
            cp16(&Bs2[row * BS2_LD + ch * 2],
                 &Bw[(size_t)(ktp + row) * N + bn + ch * 2]);
        }
    };
    auto storeA = [&](int s) {
        uint2* As2 = stageA(s);
#pragma unroll
        for (int i = 0; i < 4; i++) {
            int idx = tid + i * 256;
            int row = idx >> 3;
            int c4  = idx & 7;
            float4 v = apf[i];
            unsigned hi01, lo01, hi23, lo23;
            bsplit2(v.x, v.y, hi01, lo01);
            bsplit2(v.z, v.w, hi23, lo23);
            *(uint4*)&As2[row * AS2_LD + c4 * 2] = make_uint4(hi01, lo01, hi23, lo23);
        }
    };

    ldgA(0);
    issueB(0, 0);
    cp_commit();
    storeA(0);
    cp_wait<0>();
    __syncthreads();

    const int n_tiles = K / GBK;
    for (int t = 0; t < n_tiles; t++) {
        const bool has_next = (t + 1) < n_tiles;
        if (has_next) {
            ldgA((t + 1) * GBK);
            issueB((t + 1) * GBK, (t + 1) & 1);
            cp_commit();
        }

        const uint2* As2 = stageA(t & 1);
        const uint2* Bs2 = stageB(t & 1);

#pragma unroll
        for (int s = 0; s < 2; s++) {
            const int kb = s * 8;
            unsigned ahi[4][4], alo[4][4];
#pragma unroll
            for (int mt = 0; mt < 4; mt++) {
                const int r0 = (rb + mt * 16 + g) * AS2_LD + kb;
                uint2 v0 = As2[r0 + tig];
                uint2 v1 = As2[r0 + 8 * AS2_LD + tig];
                uint2 v2 = As2[r0 + tig + 4];
                uint2 v3 = As2[r0 + 8 * AS2_LD + tig + 4];
                ahi[mt][0] = v0.x; alo[mt][0] = v0.y;
                ahi[mt][1] = v1.x; alo[mt][1] = v1.y;
                ahi[mt][2] = v2.x; alo[mt][2] = v2.y;
                ahi[mt][3] = v3.x; alo[mt][3] = v3.y;
            }
            unsigned bhi[4][2], blo[4][2];
#pragma unroll
            for (int nt = 0; nt < 4; nt++) {
                const int c0 = cb + nt * 8 + g;
                uint2 bb0 = Bs2[(kb + tig) * BS2_LD + c0];
                uint2 bb1 = Bs2[(kb + tig + 4) * BS2_LD + c0];
                bhi[nt][0] = bb0.x; blo[nt][0] = bb0.y;
                bhi[nt][1] = bb1.x; blo[nt][1] = bb1.y;
            }
#pragma unroll
            for (int mt = 0; mt < 4; mt++)
#pragma unroll
                for (int nt = 0; nt < 4; nt++) {
                    mma_bf16(acc[mt][nt], ahi[mt], bhi[nt]);
                    mma_bf16(acc[mt][nt], ahi[mt], blo[nt]);
                    mma_bf16(acc[mt][nt], alo[mt], bhi[nt]);
                }
        }

        if (has_next) {
            storeA((t + 1) & 1);
            cp_wait<0>();
            __syncthreads();
        }
    }

#pragma unroll
    for (int nt = 0; nt < 4; nt++) {
        const int col = bn + cb + nt * 8 + tig * 2;
        const float bv0 = bias[col];
        const float bv1 = bias[col + 1];
#pragma unroll
        for (int mt = 0; mt < 4; mt++) {
            const int row0 = bm + rb + mt * 16 + g;
            const int row1 = row0 + 8;
            const float4 a = acc[mt][nt];
            if (MODE != 1) {
                if (row0 < M) {
                    float2 o = make_float2(a.x + bv0, a.y + bv1);
                    *(float2*)&C[(size_t)row0 * N + col] = o;
                }
                if (row1 < M) {
                    float2 o = make_float2(a.z + bv0, a.w + bv1);
                    *(float2*)&C[(size_t)row1 * N + col] = o;
                }
            } else {
                if (row0 < M) {
                    size_t base = (size_t)row0 * N + col;
                    float2 zi = *(const float2*)&Zi[base];
                    float2 zj = *(const float2*)&Zj[base];
                    float g0 = 1.f / (1.f + __expf(-(a.x + bv0)));
                    float g1 = 1.f / (1.f + __expf(-(a.y + bv1)));
                    float2 o = make_float2(g0 * zi.x + (1.f - g0) * zj.x,
                                           g1 * zi.y + (1.f - g1) * zj.y);
                    *(float2*)&C[base] = o;
                }
                if (row1 < M) {
                    size_t base = (size_t)row1 * N + col;
                    float2 zi = *(const float2*)&Zi[base];
                    float2 zj = *(const float2*)&Zj[base];
                    float g0 = 1.f / (1.f + __expf(-(a.z + bv0)));
                    float g1 = 1.f / (1.f + __expf(-(a.w + bv1)));
                    float2 o = make_float2(g0 * zi.x + (1.f - g0) * zj.x,
                                           g1 * zi.y + (1.f - g1) * zj.y);
                    *(float2*)&C[base] = o;
                }
            }
        }
    }
}

// ---------------- MMA attention (3xBF16 m16n8k16) ----------------------------
// One CTA per (bt,h), 8 warps; warp w owns rows n = w + 8r, r=0..31.
// Ks2[m][kp]  : packed bf16 hi/lo of K[m][2kp..2kp+1],  stride 20 uint2
// Vs2[mp][d]  : packed bf16 hi/lo of V[2mp..2mp+1][d],  stride 36 uint2
// Vpan[w][kp'][d]: pack(V[w+16kp'][d], V[w+16kp'+8][d]) for the intra panel
#define KP_LD 20
#define VP_LD 36
#define VN_LD 36
#define P_LD 40     // f32 stride
#define ATTN_SMEM ((224*KP_LD + 112*VP_LD + 8*16*VN_LD)*8 + 8*32*P_LD*4*2) // 186880

__global__ __launch_bounds__(256)
void attn_mma(const float* __restrict__ Q, const float* __restrict__ K,
              const float* __restrict__ V,
              float* __restrict__ Zi, float* __restrict__ Zj)
{
    extern __shared__ char smraw[];
    uint2* Ks2  = (uint2*)smraw;                 // [224][20]
    uint2* Vs2  = Ks2 + 224 * KP_LD;             // [112][36]
    uint2* Vpan = Vs2 + 112 * VP_LD;             // [8*16][36]
    float* Pw   = (float*)(Vpan + 8 * 16 * VN_LD);
    float* Piw  = Pw + 8 * 32 * P_LD;

    const int bt = blockIdx.x >> 3;
    const int h  = blockIdx.x & 7;
    const size_t base = ((size_t)bt * NNODE) * DMODEL + h * DHEAD;
    const int tid = threadIdx.x;
    const int w = tid >> 5, lane = tid & 31;
    const int g = lane >> 2, tig = lane & 3;

    // ---- stage K pairs
    for (int idx = tid; idx < 224 * 16; idx += 256) {
        int m = idx >> 4, kp = idx & 15;
        float2 kv = make_float2(0.f, 0.f);
        if (m < NNODE) kv = *(const float2*)&K[base + (size_t)m * DMODEL + 2 * kp];
        unsigned hi, lo; bsplit2(kv.x, kv.y, hi, lo);
        Ks2[m * KP_LD + kp] = make_uint2(hi, lo);
    }
    // ---- stage V pairs (m, m+1)
    for (int idx = tid; idx < 112 * 32; idx += 256) {
        int mp = idx >> 5, d = idx & 31;
        int m0 = 2 * mp, m1 = m0 + 1;
        float v0 = (m0 < NNODE) ? V[base + (size_t)m0 * DMODEL + d] : 0.f;
        float v1 = (m1 < NNODE) ? V[base + (size_t)m1 * DMODEL + d] : 0.f;
        unsigned hi, lo; bsplit2(v0, v1, hi, lo);
        Vs2[mp * VP_LD + d] = make_uint2(hi, lo);
    }
    // ---- stage intra V panel: pairs (w+16kp', w+16kp'+8)
    for (int idx = tid; idx < 8 * 16 * 32; idx += 256) {
        int wp = idx >> 9, rest = idx & 511, kp = rest >> 5, d = rest & 31;
        int m0 = wp + 16 * kp, m1 = m0 + 8;
        float v0 = (m0 < NNODE) ? V[base + (size_t)m0 * DMODEL + d] : 0.f;
        float v1 = (m1 < NNODE) ? V[base + (size_t)m1 * DMODEL + d] : 0.f;
        unsigned hi, lo; bsplit2(v0, v1, hi, lo);
        Vpan[(wp * 16 + kp) * VN_LD + d] = make_uint2(hi, lo);
    }

    float* myP  = Pw  + w * (32 * P_LD);
    float* myPi = Piw + w * (32 * P_LD);
    const uint2* myVpan = Vpan + (w * 16) * VN_LD;
    for (int i = lane; i < 32 * P_LD; i += 32) myPi[i] = 0.f;

    // ---- Q fragments (bf16 hi/lo, scale folded in)
    const float scale = 0.1767766952966369f; // 1/sqrt(32)
    unsigned qh[2][2][4], ql[2][2][4];
#pragma unroll
    for (int mt = 0; mt < 2; mt++)
#pragma unroll
        for (int s = 0; s < 2; s++) {
            int r0 = mt * 16 + g, r1 = r0 + 8;
            int n0 = w + 8 * r0; if (n0 > 206) n0 = 206;
            int n1 = w + 8 * r1; if (n1 > 206) n1 = 206;
            int k0 = 16 * s + 2 * tig;
            float2 q00 = *(const float2*)&Q[base + (size_t)n0 * DMODEL + k0];
            float2 q10 = *(const float2*)&Q[base + (size_t)n1 * DMODEL + k0];
            float2 q01 = *(const float2*)&Q[base + (size_t)n0 * DMODEL + k0 + 8];
            float2 q11 = *(const float2*)&Q[base + (size_t)n1 * DMODEL + k0 + 8];
            bsplit2(q00.x * scale, q00.y * scale, qh[mt][s][0], ql[mt][s][0]);
            bsplit2(q10.x * scale, q10.y * scale, qh[mt][s][1], ql[mt][s][1]);
            bsplit2(q01.x * scale, q01.y * scale, qh[mt][s][2], ql[mt][s][2]);
            bsplit2(q11.x * scale, q11.y * scale, qh[mt][s][3], ql[mt][s][3]);
        }
    __syncthreads();

    float4 zall[2][4], zint[2][4];
#pragma unroll
    for (int mt = 0; mt < 2; mt++)
#pragma unroll
        for (int nt = 0; nt < 4; nt++) {
            zall[mt][nt] = make_float4(0.f, 0.f, 0.f, 0.f);
            zint[mt][nt] = make_float4(0.f, 0.f, 0.f, 0.f);
        }
    float sa[4] = {0.f, 0.f, 0.f, 0.f};
    float si[4] = {0.f, 0.f, 0.f, 0.f};
    const bool isHolder = (tig == (w >> 1));
    const int wodd = w & 1;

    for (int ct = 0; ct < 7; ct++) {
        const int mbase = 32 * ct;

        // ---- S = (Q*scale)·K^T
        float4 sacc[2][4];
#pragma unroll
        for (int mt = 0; mt < 2; mt++)
#pragma unroll
            for (int nt = 0; nt < 4; nt++) sacc[mt][nt] = make_float4(0.f, 0.f, 0.f, 0.f);

#pragma unroll
        for (int s = 0; s < 2; s++)
#pragma unroll
            for (int nt = 0; nt < 4; nt++) {
                int mrow = (mbase + 8 * nt + g) * KP_LD;
                uint2 kb0 = Ks2[mrow + 8 * s + tig];
                uint2 kb1 = Ks2[mrow + 8 * s + tig + 4];
                unsigned bh[2] = {kb0.x, kb1.x};
                unsigned bl[2] = {kb0.y, kb1.y};
#pragma unroll
                for (int mt = 0; mt < 2; mt++) {
                    mma_bf16(sacc[mt][nt], qh[mt][s], bh);
                    mma_bf16(sacc[mt][nt], qh[mt][s], bl);
                    mma_bf16(sacc[mt][nt], ql[mt][s], bh);
                }
            }

        // ---- mask + exp + sums + stage P (and intra panel)
#pragma unroll
        for (int mt = 0; mt < 2; mt++)
#pragma unroll
            for (int nt = 0; nt < 4; nt++) {
                float4 c = sacc[mt][nt];
                int m0 = mbase + 8 * nt + 2 * tig, m1 = m0 + 1;
                int r0 = mt * 16 + g, r1 = r0 + 8;
                int n0 = w + 8 * r0, n1 = w + 8 * r1;
                c.x = (m0 <= 206 && m0 != n0) ? __expf(c.x) : 0.f;
                c.y = (m1 <= 206 && m1 != n0) ? __expf(c.y) : 0.f;
                c.z = (m0 <= 206 && m0 != n1) ? __expf(c.z) : 0.f;
                c.w = (m1 <= 206 && m1 != n1) ? __expf(c.w) : 0.f;
                sa[mt * 2 + 0] += c.x + c.y;
                sa[mt * 2 + 1] += c.z + c.w;
                if (isHolder) {
                    float v0 = wodd ? c.y : c.x;
                    float v1 = wodd ? c.w : c.z;
                    si[mt * 2 + 0] += v0;
                    si[mt * 2 + 1] += v1;
                    myPi[r0 * P_LD + 4 * ct + nt] = v0;
                    myPi[r1 * P_LD + 4 * ct + nt] = v1;
                }
                *(float2*)&myP[r0 * P_LD + 8 * nt + 2 * tig] = make_float2(c.x, c.y);
                *(float2*)&myP[r1 * P_LD + 8 * nt + 2 * tig] = make_float2(c.z, c.w);
            }
        __syncwarp();

        // ---- z_all += P · V
#pragma unroll
        for (int s = 0; s < 2; s++) {
            unsigned ah[2][4], al[2][4];
#pragma unroll
            for (int mt = 0; mt < 2; mt++) {
                int r0 = (mt * 16 + g) * P_LD, r1 = r0 + 8 * P_LD;
                int k0 = 16 * s + 2 * tig;
                float2 p00 = *(const float2*)&myP[r0 + k0];
                float2 p10 = *(const float2*)&myP[r1 + k0];
                float2 p01 = *(const float2*)&myP[r0 + k0 + 8];
                float2 p11 = *(const float2*)&myP[r1 + k0 + 8];
                bsplit2(p00.x, p00.y, ah[mt][0], al[mt][0]);
                bsplit2(p10.x, p10.y, ah[mt][1], al[mt][1]);
                bsplit2(p01.x, p01.y, ah[mt][2], al[mt][2]);
                bsplit2(p11.x, p11.y, ah[mt][3], al[mt][3]);
            }
            const int mpb = (mbase >> 1) + 8 * s;
#pragma unroll
            for (int nt = 0; nt < 4; nt++) {
                uint2 vb0 = Vs2[(mpb + tig) * VP_LD + 8 * nt + g];
                uint2 vb1 = Vs2[(mpb + tig + 4) * VP_LD + 8 * nt + g];
                unsigned bh[2] = {vb0.x, vb1.x};
                unsigned bl[2] = {vb0.y, vb1.y};
#pragma unroll
                for (int mt = 0; mt < 2; mt++) {
                    mma_bf16(zall[mt][nt], ah[mt], bh);
                    mma_bf16(zall[mt][nt], ah[mt], bl);
                    mma_bf16(zall[mt][nt], al[mt], bh);
                }
            }
        }
        __syncwarp();
    }

    // ---- z_intra = P_intra · V_panel
#pragma unroll
    for (int s = 0; s < 2; s++) {
        unsigned ah[2][4], al[2][4];
#pragma unroll
        for (int mt = 0; mt < 2; mt++) {
            int r0 = (mt * 16 + g) * P_LD, r1 = r0 + 8 * P_LD;
            int k0 = 16 * s + 2 * tig;
            float2 p00 = *(const float2*)&myPi[r0 + k0];
            float2 p10 = *(const float2*)&myPi[r1 + k0];
            float2 p01 = *(const float2*)&myPi[r0 + k0 + 8];
            float2 p11 = *(const float2*)&myPi[r1 + k0 + 8];
            bsplit2(p00.x, p00.y, ah[mt][0], al[mt][0]);
            bsplit2(p10.x, p10.y, ah[mt][1], al[mt][1]);
            bsplit2(p01.x, p01.y, ah[mt][2], al[mt][2]);
            bsplit2(p11.x, p11.y, ah[mt][3], al[mt][3]);
        }
#pragma unroll
        for (int nt = 0; nt < 4; nt++) {
            uint2 vb0 = myVpan[(8 * s + tig) * VN_LD + 8 * nt + g];
            uint2 vb1 = myVpan[(8 * s + tig + 4) * VN_LD + 8 * nt + g];
            unsigned bh[2] = {vb0.x, vb1.x};
            unsigned bl[2] = {vb0.y, vb1.y};
#pragma unroll
            for (int mt = 0; mt < 2; mt++) {
                mma_bf16(zint[mt][nt], ah[mt], bh);
                mma_bf16(zint[mt][nt], ah[mt], bl);
                mma_bf16(zint[mt][nt], al[mt], bh);
            }
        }
    }

    // ---- row-sum reduce over the tig quad
    float ri[4], rj[4];
#pragma unroll
    for (int i = 0; i < 4; i++) {
        float a = sa[i], s = si[i];
        a += __shfl_xor_sync(0xffffffffu, a, 1);
        a += __shfl_xor_sync(0xffffffffu, a, 2);
        s += __shfl_xor_sync(0xffffffffu, s, 1);
        s += __shfl_xor_sync(0xffffffffu, s, 2);
        ri[i] = 1.f / s;
        rj[i] = 1.f / (a - s);
    }

    // ---- normalize + transpose via smem, coalesced stores
    __syncwarp();
#pragma unroll
    for (int mt = 0; mt < 2; mt++)
#pragma unroll
        for (int nt = 0; nt < 4; nt++) {
            int r0 = mt * 16 + g, r1 = r0 + 8;
            float4 za = zall[mt][nt], zi4 = zint[mt][nt];
            float ri0 = ri[mt * 2], ri1 = ri[mt * 2 + 1];
            float rj0 = rj[mt * 2], rj1 = rj[mt * 2 + 1];
            *(float2*)&myP [r0 * P_LD + 8 * nt + 2 * tig] = make_float2(zi4.x * ri0, zi4.y * ri0);
            *(float2*)&myP [r1 * P_LD + 8 * nt + 2 * tig] = make_float2(zi4.z * ri1, zi4.w * ri1);
            *(float2*)&myPi[r0 * P_LD + 8 * nt + 2 * tig] = make_float2((za.x - zi4.x) * rj0, (za.y - zi4.y) * rj0);
            *(float2*)&myPi[r1 * P_LD + 8 * nt + 2 * tig] = make_float2((za.z - zi4.z) * rj1, (za.w - zi4.w) * rj1);
        }
    __syncwarp();
#pragma unroll 4
    for (int rr = 0; rr < 32; rr++) {
        int n = w + 8 * rr;
        if (n < NNODE) {
            Zi[base + (size_t)n * DMODEL + lane] = myP [rr * P_LD + lane];
            Zj[base + (size_t)n * DMODEL + lane] = myPi[rr * P_LD + lane];
        }
    }
}

// ---------------- launch --------------------------------------------------
extern "C" void kernel_launch(void* const* d_in, const int* in_sizes, int n_in,
                              void* d_out, int out_size)
{
    const float* x  = (const float*)d_in[0];
    const float* Wq = (const float*)d_in[1];
    const float* bq = (const float*)d_in[2];
    const float* Wk = (const float*)d_in[3];
    const float* bk = (const float*)d_in[4];
    const float* Wv = (const float*)d_in[5];
    const float* bv = (const float*)d_in[6];
    const float* Wg = (const float*)d_in[7];
    const float* bg = (const float*)d_in[8];
    const float* Wp = (const float*)d_in[9];
    const float* bp = (const float*)d_in[10];
    float* out = (float*)d_out;

    float *Q, *Kp, *Vp, *Zi, *Zj, *Zc;
    uint2 *W2;
    cudaGetSymbolAddress((void**)&Q,  g_Q);
    cudaGetSymbolAddress((void**)&Kp, g_K);
    cudaGetSymbolAddress((void**)&Vp, g_V);
    cudaGetSymbolAddress((void**)&Zi, g_Zi);
    cudaGetSymbolAddress((void**)&Zj, g_Zj);
    cudaGetSymbolAddress((void**)&Zc, g_Zc);
    cudaGetSymbolAddress((void**)&W2, g_W2);

    cudaFuncSetAttribute(gemm_tc<0>, cudaFuncAttributeMaxDynamicSharedMemorySize, GEMM_SMEM);
    cudaFuncSetAttribute(gemm_tc<1>, cudaFuncAttributeMaxDynamicSharedMemorySize, GEMM_SMEM);
    cudaFuncSetAttribute(gemm_tc<2>, cudaFuncAttributeMaxDynamicSharedMemorySize, GEMM_SMEM);
    cudaFuncSetAttribute(attn_mma,   cudaFuncAttributeMaxDynamicSharedMemorySize, ATTN_SMEM);

    const int mblocks = (MTOT + GBM - 1) / GBM;   // 311

    split_weights<<<(WP_TOTAL + 255) / 256, 256>>>(Wq, Wk, Wv, Wp, Wg);

    gemm_tc<2><<<dim3(mblocks, 6), 256, GEMM_SMEM>>>(
        x, nullptr, W2 + OFFP_WQ, bq, bk, bv,
        nullptr, nullptr, Q, Kp, Vp, MTOT, DMODEL);

    attn_mma<<<BTT * NHEADS, 256, ATTN_SMEM>>>(Q, Kp, Vp, Zi, Zj);

    gemm_tc<1><<<dim3(mblocks, 2), 256, GEMM_SMEM>>>(
        Zi, Zj, W2 + OFFP_WG, bg, nullptr, nullptr,
        Zi, Zj, Zc, nullptr, nullptr, MTOT, 2 * DMODEL);

    gemm_tc<0><<<dim3(mblocks, 2), 256, GEMM_SMEM>>>(
        Zc, nullptr, W2 + OFFP_WP, bp, nullptr, nullptr,
        nullptr, nullptr, out, nullptr, nullptr, MTOT, DMODEL);
}